// round 3
// baseline (speedup 1.0000x reference)
#include <cuda_runtime.h>
#include <cuda_bf16.h>
#include <math.h>

// ============================================================================
// Sinkhorn divergence (geomloss 'sinkhorn', p=2, blur=0.05, scaling=0.9),
// debiased, log-domain softmin with eps annealing.
//
// x,y: [B=4, C=64, H=64, W=64] fp32 -> point clouds [B, N=4096, D=64],
// where point n's coordinate c lives at x[b*C*HW + c*HW + n] (n contiguous).
//
// Pipeline per launch:
//   1. norms:   |p_i|^2 for all points                  (tiny)
//   2. cost:    C[b][m][i][j] = 0.5(|u_i|^2+|v_j|^2) - u_i.v_j  for
//               m = 0:xy 1:yx 2:xx 3:yy   -> 1 GB static scratch
//   3. softmin init (eps0=256)
//   4. 56 annealing steps (ping-pong potential buffers)
//   5. final extrapolation at eps=0.0025
//   6. deterministic reduction -> scalar loss
// ============================================================================

#define NPTS 4096
#define DDIM 64
#define NB   4

// 16 matrices x 4096^2 floats = 1 GiB static scratch (allowed: __device__ global)
__device__ float g_C[(size_t)16 * NPTS * NPTS];
// potentials: [pingpong][batch][{f_ba,g_ab,f_aa,g_bb}][NPTS]
__device__ float g_pot[2][NB][4][NPTS];
// final extrapolated potentials
__device__ float g_potF[NB][4][NPTS];
// squared norms: [which(x=0,y=1)][batch][NPTS]
__device__ float g_norm[2][NB][NPTS];

__device__ __forceinline__ float ex2f(float x) {
    float r;
    asm("ex2.approx.ftz.f32 %0, %1;" : "=f"(r) : "f"(x));
    return r;
}

// ---------------------------------------------------------------------------
// Squared norms of all points.
// ---------------------------------------------------------------------------
__global__ void __launch_bounds__(256) norm_kernel(const float* __restrict__ x,
                                                   const float* __restrict__ y) {
    int t = blockIdx.x * 256 + threadIdx.x;          // t < 2*4*4096 = 32768
    int i = t & (NPTS - 1);
    int b = (t >> 12) & 3;
    int which = t >> 14;
    const float* p = (which ? y : x) + (size_t)b * DDIM * NPTS + i;
    float s = 0.f;
#pragma unroll
    for (int c = 0; c < DDIM; ++c) {
        float v = p[(size_t)c * NPTS];
        s = fmaf(v, v, s);
    }
    g_norm[which][b][i] = s;
}

// ---------------------------------------------------------------------------
// Cost matrices via fp32 tiled GEMM on CUDA cores (accuracy critical).
// Tile 64x64, K=64 fully resident in smem. grid = (64, 64, 16).
// ---------------------------------------------------------------------------
__global__ void __launch_bounds__(256) cost_kernel(const float* __restrict__ x,
                                                   const float* __restrict__ y) {
    const int which = blockIdx.z & 3;
    const int b = blockIdx.z >> 2;
    const float* u = (which == 1 || which == 3) ? y : x;   // 0:x 1:y 2:x 3:y
    const float* v = (which == 0 || which == 3) ? y : x;   // 0:y 1:x 2:x 3:y
    const float* nu = g_norm[(which == 1 || which == 3) ? 1 : 0][b];
    const float* nv = g_norm[(which == 0 || which == 3) ? 1 : 0][b];
    u += (size_t)b * DDIM * NPTS;
    v += (size_t)b * DDIM * NPTS;

    const int I = blockIdx.x * 64;
    const int J = blockIdx.y * 64;

    __shared__ float Us[DDIM][64];
    __shared__ float Vs[DDIM][64];
    for (int idx = threadIdx.x; idx < DDIM * 64; idx += 256) {
        int c = idx >> 6, i = idx & 63;
        Us[c][i] = u[(size_t)c * NPTS + I + i];
        Vs[c][i] = v[(size_t)c * NPTS + J + i];
    }
    __syncthreads();

    const int tx = threadIdx.x & 15;   // j micro-tile
    const int ty = threadIdx.x >> 4;   // i micro-tile
    float acc[4][4] = {};
#pragma unroll 8
    for (int k = 0; k < DDIM; ++k) {
        float4 a  = *(const float4*)&Us[k][ty * 4];
        float4 bb = *(const float4*)&Vs[k][tx * 4];
        acc[0][0] = fmaf(a.x, bb.x, acc[0][0]);
        acc[0][1] = fmaf(a.x, bb.y, acc[0][1]);
        acc[0][2] = fmaf(a.x, bb.z, acc[0][2]);
        acc[0][3] = fmaf(a.x, bb.w, acc[0][3]);
        acc[1][0] = fmaf(a.y, bb.x, acc[1][0]);
        acc[1][1] = fmaf(a.y, bb.y, acc[1][1]);
        acc[1][2] = fmaf(a.y, bb.z, acc[1][2]);
        acc[1][3] = fmaf(a.y, bb.w, acc[1][3]);
        acc[2][0] = fmaf(a.z, bb.x, acc[2][0]);
        acc[2][1] = fmaf(a.z, bb.y, acc[2][1]);
        acc[2][2] = fmaf(a.z, bb.z, acc[2][2]);
        acc[2][3] = fmaf(a.z, bb.w, acc[2][3]);
        acc[3][0] = fmaf(a.w, bb.x, acc[3][0]);
        acc[3][1] = fmaf(a.w, bb.y, acc[3][1]);
        acc[3][2] = fmaf(a.w, bb.z, acc[3][2]);
        acc[3][3] = fmaf(a.w, bb.w, acc[3][3]);
    }

    float* Cout = g_C + ((size_t)(b * 4 + which) << 24);
    float nvv[4];
#pragma unroll
    for (int q = 0; q < 4; ++q) nvv[q] = nv[J + tx * 4 + q];
#pragma unroll
    for (int ii = 0; ii < 4; ++ii) {
        int row = I + ty * 4 + ii;
        float nr = nu[row];
        float4 w;
        w.x = 0.5f * (nr + nvv[0]) - acc[ii][0];
        w.y = 0.5f * (nr + nvv[1]) - acc[ii][1];
        w.z = 0.5f * (nr + nvv[2]) - acc[ii][2];
        w.w = 0.5f * (nr + nvv[3]) - acc[ii][3];
        *(float4*)&Cout[(size_t)row * NPTS + J + tx * 4] = w;
    }
}

// ---------------------------------------------------------------------------
// Softmin sweep: one kernel updates all 4 potentials for all 4 batches.
// grid = (128 rowblocks, 4 matrices, 4 batches); 256 threads; warp = row.
// mode: 0=init (h = b_log), 1=step (h = b_log + pot/eps; out = 0.5(old+new)),
//       2=final (h = b_log + pot/eps; out -> g_potF).
// All math in base-2: arg2 = h*log2e - C*(log2e/eps);  -log(4096)*log2e = -12.
// ---------------------------------------------------------------------------
__global__ void __launch_bounds__(256) softmin_kernel(float eps, int mode,
                                                      int src, int dst) {
    const int m = blockIdx.y;
    const int b = blockIdx.z;
    const float L2E = 1.4426950408889634f;
    const float LN2 = 0.6931471805599453f;
    const float ieps2 = L2E / eps;

    // h-source potential per matrix: xy<-g_ab, yx<-f_ba, xx<-f_aa, yy<-g_bb
    const int hsrc = (m == 0) ? 1 : (m == 1) ? 0 : m;
    const float* __restrict__ pin_h = &g_pot[src][b][hsrc][0];
    const float* __restrict__ pin_o = &g_pot[src][b][m][0];
    float* __restrict__ pout = (mode == 2) ? &g_potF[b][m][0]
                                           : &g_pot[dst][b][m][0];
    const float4* __restrict__ C4 =
        (const float4*)(g_C + ((size_t)(b * 4 + m) << 24));

    __shared__ float4 h4[NPTS / 4];
    {
        float* hs = (float*)h4;
        for (int j = threadIdx.x; j < NPTS; j += 256) {
            float hv = -12.0f;                      // -log(4096)*log2(e)
            if (mode != 0) hv = fmaf(pin_h[j], ieps2, -12.0f);
            hs[j] = hv;
        }
    }
    __syncthreads();

    const int warp = threadIdx.x >> 5;
    const int lane = threadIdx.x & 31;
    const int row0 = blockIdx.x * 32;

#pragma unroll 1
    for (int it = 0; it < 4; ++it) {
        const int row = row0 + it * 8 + warp;
        const float4* __restrict__ Crow = C4 + (size_t)row * (NPTS / 4);
        float mx = -1e30f;
        float s = 0.f;
#pragma unroll 4
        for (int c = lane; c < NPTS / 4; c += 32) {
            float4 cv = Crow[c];
            float4 hv = h4[c];
            float a0 = fmaf(cv.x, -ieps2, hv.x);
            float a1 = fmaf(cv.y, -ieps2, hv.y);
            float a2 = fmaf(cv.z, -ieps2, hv.z);
            float a3 = fmaf(cv.w, -ieps2, hv.w);
            float cm = fmaxf(fmaxf(a0, a1), fmaxf(a2, a3));
            float nm = fmaxf(mx, cm);
            float e = ex2f(a0 - nm) + ex2f(a1 - nm) + ex2f(a2 - nm) + ex2f(a3 - nm);
            s = fmaf(s, ex2f(mx - nm), e);
            mx = nm;
        }
        // warp-level merge of (max, sum) pairs
#pragma unroll
        for (int off = 16; off; off >>= 1) {
            float om = __shfl_xor_sync(0xffffffffu, mx, off);
            float os = __shfl_xor_sync(0xffffffffu, s, off);
            float nm = fmaxf(mx, om);
            s = fmaf(s, ex2f(mx - nm), os * ex2f(om - nm));
            mx = nm;
        }
        if (lane == 0) {
            float lse_nat = (mx + log2f(s)) * LN2;
            float res = -eps * lse_nat;
            if (mode == 1) res = 0.5f * (pin_o[row] + res);
            pout[row] = res;
        }
    }
}

// ---------------------------------------------------------------------------
// Deterministic reduction: loss = [sum_b mean_i(f_ba-f_aa) + mean_j(g_ab-g_bb)]/B
// ---------------------------------------------------------------------------
__global__ void __launch_bounds__(256) reduce_kernel(float* __restrict__ out) {
    __shared__ float sm[256];
    const float* p = &g_potF[0][0][0];
    float acc = 0.f;
    for (int idx = threadIdx.x; idx < NB * 4 * NPTS; idx += 256) {
        int mm = (idx / NPTS) & 3;
        float v = p[idx];
        acc += (mm < 2) ? v : -v;   // f_ba_f,g_ab_f positive; f_aa_f,g_bb_f negative
    }
    sm[threadIdx.x] = acc;
    __syncthreads();
    for (int sft = 128; sft; sft >>= 1) {
        if (threadIdx.x < sft) sm[threadIdx.x] += sm[threadIdx.x + sft];
        __syncthreads();
    }
    if (threadIdx.x == 0) out[0] = sm[0] / ((float)NPTS * (float)NB);
}

// ---------------------------------------------------------------------------
extern "C" void kernel_launch(void* const* d_in, const int* in_sizes, int n_in,
                              void* d_out, int out_size) {
    const float* x = (const float*)d_in[0];
    const float* y = (const float*)d_in[1];

    // eps schedule: exp(arange(2 log 16, 2 log 0.05, 2 log 0.9)) ++ [0.05^2]
    float epsl[56];
    {
        double st = 2.0 * log(16.0);
        double sp = 2.0 * log(0.9);
        for (int k = 0; k < 55; ++k) epsl[k] = (float)exp(st + k * sp);
        epsl[55] = 0.0025f;
    }

    norm_kernel<<<(2 * NB * NPTS) / 256, 256>>>(x, y);
    cost_kernel<<<dim3(64, 64, 16), 256>>>(x, y);

    dim3 sg(NPTS / 32, 4, NB);
    // init at eps0, writes buffer 0
    softmin_kernel<<<sg, 256>>>(epsl[0], 0, 0, 0);
    // 56 annealing steps, ping-pong; step s reads s&1, writes (s+1)&1
    for (int s = 0; s < 56; ++s)
        softmin_kernel<<<sg, 256>>>(epsl[s], 1, s & 1, (s + 1) & 1);
    // converged potentials are in buffer 0 after 56 steps
    softmin_kernel<<<sg, 256>>>(0.0025f, 2, 0, 0);

    reduce_kernel<<<1, 256>>>((float*)d_out);
}